// round 5
// baseline (speedup 1.0000x reference)
#include <cuda_runtime.h>

#define POOL 7
#define FM_W 64
#define C_VEC 32          // 128 fp32 channels = 32 float4

__global__ __launch_bounds__(224, 8)
void roi_pool_kernel(const float4* __restrict__ fm4,
                     const int* __restrict__ rois,
                     float4* __restrict__ out4,
                     int n_rois)
{
    const int roi = blockIdx.x;
    if (roi >= n_rois) return;

    __shared__ int   s_y0[POOL], s_y1[POOL], s_x0[POOL], s_x1[POOL];
    __shared__ float s_wy[POOL], s_wx[POOL];
    __shared__ int4   s_off[POOL * POOL];   // 4 gather offsets per position (float4 units)
    __shared__ float4 s_wgt[POOL * POOL];   // factored bilinear weights per position

    const int t = threadIdx.x;

    // ---- Phase 1: 1-D sample grids (exactly matches reference math) ----
    if (t < POOL) {
        const int ry1 = rois[roi * 4 + 1];
        const int ry2 = rois[roi * 4 + 3];
        int hh = max(ry2 - ry1, 1);
        float hf = (float)hh;
        float yc = __fdiv_rn(((float)t + 0.5f) * hf, (float)POOL) - 0.5f;
        yc = fminf(fmaxf(yc, 0.0f), hf - 1.0f);
        int y0 = (int)floorf(yc);
        s_y0[t] = y0 + ry1;
        s_y1[t] = min(y0 + 1, hh - 1) + ry1;
        s_wy[t] = yc - (float)y0;
    } else if (t >= 32 && t < 32 + POOL) {
        const int j = t - 32;
        const int rx1 = rois[roi * 4 + 0];
        const int rx2 = rois[roi * 4 + 2];
        int ww = max(rx2 - rx1, 1);
        float wf = (float)ww;
        float xc = __fdiv_rn(((float)j + 0.5f) * wf, (float)POOL) - 0.5f;
        xc = fminf(fmaxf(xc, 0.0f), wf - 1.0f);
        int x0 = (int)floorf(xc);
        s_x0[j] = x0 + rx1;
        s_x1[j] = min(x0 + 1, ww - 1) + rx1;
        s_wx[j] = xc - (float)x0;
    }
    __syncthreads();

    // ---- Phase 2: per-position offsets + factored weights ----
    if (t < POOL * POOL) {
        const int py = t / POOL;
        const int px = t - py * POOL;

        const int rb0 = s_y0[py] * FM_W;
        const int rb1 = s_y1[py] * FM_W;
        const int xa0 = s_x0[px];
        const int xa1 = s_x1[px];

        int4 o;
        o.x = (rb0 + xa0) * C_VEC;
        o.y = (rb0 + xa1) * C_VEC;
        o.z = (rb1 + xa0) * C_VEC;
        o.w = (rb1 + xa1) * C_VEC;
        s_off[t] = o;

        const int rx1 = rois[roi * 4 + 0];
        const int ry1 = rois[roi * 4 + 1];
        const int rx2 = rois[roi * 4 + 2];
        const int ry2 = rois[roi * 4 + 3];
        const float live = ((rx1 | ry1 | rx2 | ry2) == 0) ? 0.0f : 1.0f;

        const float wy = s_wy[py];
        const float wx = s_wx[px];
        float4 w;
        w.x = (1.0f - wy) * (1.0f - wx) * live;  // g00
        w.y = (1.0f - wy) * wx * live;           // g01
        w.z = wy * (1.0f - wx) * live;           // g10
        w.w = wy * wx * live;                    // g11
        s_wgt[t] = w;
    }
    __syncthreads();

    // ---- Main: warp w owns output row py = w; lanes cover 128 channels ----
    const int warp = t >> 5;   // 0..6
    const int lane = t & 31;

    float4* optr = out4 + (size_t)roi * (POOL * POOL * C_VEC)
                        + warp * (POOL * C_VEC) + lane;

#pragma unroll
    for (int px = 0; px < POOL; px++) {
        const int p = warp * POOL + px;
        const int4   o = s_off[p];
        const float4 w = s_wgt[p];

        const float4 g00 = __ldg(fm4 + o.x + lane);
        const float4 g01 = __ldg(fm4 + o.y + lane);
        const float4 g10 = __ldg(fm4 + o.z + lane);
        const float4 g11 = __ldg(fm4 + o.w + lane);

        float4 r;
        r.x = fmaf(g00.x, w.x, fmaf(g01.x, w.y, fmaf(g10.x, w.z, g11.x * w.w)));
        r.y = fmaf(g00.y, w.x, fmaf(g01.y, w.y, fmaf(g10.y, w.z, g11.y * w.w)));
        r.z = fmaf(g00.z, w.x, fmaf(g01.z, w.y, fmaf(g10.z, w.z, g11.z * w.w)));
        r.w = fmaf(g00.w, w.x, fmaf(g01.w, w.y, fmaf(g10.w, w.z, g11.w * w.w)));

        optr[px * C_VEC] = r;
    }
}

extern "C" void kernel_launch(void* const* d_in, const int* in_sizes, int n_in,
                              void* d_out, int out_size)
{
    const float4* fm4  = (const float4*)d_in[0];   // (1,64,64,128) fp32
    const int*    rois = (const int*)d_in[1];      // (1,N,4) int32
    float4*       out4 = (float4*)d_out;           // (1,N,7,7,128) fp32

    const int n_rois = in_sizes[1] / 4;

    roi_pool_kernel<<<n_rois, 224>>>(fm4, rois, out4, n_rois);
}

// round 6
// speedup vs baseline: 1.0708x; 1.0708x over previous
#include <cuda_runtime.h>

#define POOL 7
#define FM_W 64
#define C2   64   // float2 chunks per pixel (128 fp32 channels)

__global__ __launch_bounds__(224, 6)
void roi_pool_kernel(const float2* __restrict__ fm2,
                     const int* __restrict__ rois,
                     float2* __restrict__ out2,
                     int n_rois)
{
    const int roi = blockIdx.x;
    if (roi >= n_rois) return;

    __shared__ int4   s_off[POOL * POOL];   // 4 gather offsets (float2 units)
    __shared__ float4 s_wgt[POOL * POOL];   // factored bilinear weights

    const int t = threadIdx.x;

    // ---- Single fused precompute phase: thread t < 49 owns position t ----
    if (t < POOL * POOL) {
        const int rx1 = __ldg(rois + roi * 4 + 0);
        const int ry1 = __ldg(rois + roi * 4 + 1);
        const int rx2 = __ldg(rois + roi * 4 + 2);
        const int ry2 = __ldg(rois + roi * 4 + 3);

        const int py = t / POOL;
        const int px = t - py * POOL;

        // y axis (exactly matches reference: ((j+0.5)*hf)/7 - 0.5, clip, floor)
        const int hh = max(ry2 - ry1, 1);
        const float hf = (float)hh;
        float yc = __fdiv_rn(((float)py + 0.5f) * hf, (float)POOL) - 0.5f;
        yc = fminf(fmaxf(yc, 0.0f), hf - 1.0f);
        const int y0 = (int)floorf(yc);
        const int ya0 = y0 + ry1;
        const int ya1 = min(y0 + 1, hh - 1) + ry1;
        const float wy = yc - (float)y0;

        // x axis
        const int ww = max(rx2 - rx1, 1);
        const float wf = (float)ww;
        float xc = __fdiv_rn(((float)px + 0.5f) * wf, (float)POOL) - 0.5f;
        xc = fminf(fmaxf(xc, 0.0f), wf - 1.0f);
        const int x0 = (int)floorf(xc);
        const int xa0 = x0 + rx1;
        const int xa1 = min(x0 + 1, ww - 1) + rx1;
        const float wx = xc - (float)x0;

        int4 o;
        o.x = (ya0 * FM_W + xa0) * C2;
        o.y = (ya0 * FM_W + xa1) * C2;
        o.z = (ya1 * FM_W + xa0) * C2;
        o.w = (ya1 * FM_W + xa1) * C2;
        s_off[t] = o;

        const float live = ((rx1 | ry1 | rx2 | ry2) == 0) ? 0.0f : 1.0f;
        float4 w;
        w.x = (1.0f - wy) * (1.0f - wx) * live;  // g00
        w.y = (1.0f - wy) * wx * live;           // g01
        w.z = wy * (1.0f - wx) * live;           // g10
        w.w = wy * wx * live;                    // g11
        s_wgt[t] = w;
    }
    __syncthreads();

    // ---- Main: warp w owns output row py = w; lanes cover 128 channels as
    //      two 256B (2-line) sweeps per pixel -> all LDG.64 / STG.64 ----
    const int warp = t >> 5;   // 0..6
    const int lane = t & 31;

    float2* obase = out2 + (size_t)roi * (POOL * POOL * C2)
                         + warp * (POOL * C2) + lane;

#pragma unroll
    for (int px = 0; px < POOL; px++) {
        const int p = warp * POOL + px;
        const int4   o = s_off[p];
        const float4 w = s_wgt[p];

        // sweep A: chunks [lane]        (bytes 0..255 of each pixel)
        const float2 a00 = __ldg(fm2 + o.x + lane);
        const float2 a01 = __ldg(fm2 + o.y + lane);
        const float2 a10 = __ldg(fm2 + o.z + lane);
        const float2 a11 = __ldg(fm2 + o.w + lane);
        // sweep B: chunks [32 + lane]   (bytes 256..511 of each pixel)
        const float2 b00 = __ldg(fm2 + o.x + 32 + lane);
        const float2 b01 = __ldg(fm2 + o.y + 32 + lane);
        const float2 b10 = __ldg(fm2 + o.z + 32 + lane);
        const float2 b11 = __ldg(fm2 + o.w + 32 + lane);

        float2 ra, rb;
        ra.x = fmaf(a00.x, w.x, fmaf(a01.x, w.y, fmaf(a10.x, w.z, a11.x * w.w)));
        ra.y = fmaf(a00.y, w.x, fmaf(a01.y, w.y, fmaf(a10.y, w.z, a11.y * w.w)));
        rb.x = fmaf(b00.x, w.x, fmaf(b01.x, w.y, fmaf(b10.x, w.z, b11.x * w.w)));
        rb.y = fmaf(b00.y, w.x, fmaf(b01.y, w.y, fmaf(b10.y, w.z, b11.y * w.w)));

        obase[px * C2]      = ra;
        obase[px * C2 + 32] = rb;
    }
}

extern "C" void kernel_launch(void* const* d_in, const int* in_sizes, int n_in,
                              void* d_out, int out_size)
{
    const float2* fm2  = (const float2*)d_in[0];   // (1,64,64,128) fp32
    const int*    rois = (const int*)d_in[1];      // (1,N,4) int32
    float2*       out2 = (float2*)d_out;           // (1,N,7,7,128) fp32

    const int n_rois = in_sizes[1] / 4;

    roi_pool_kernel<<<n_rois, 224>>>(fm2, rois, out2, n_rois);
}

// round 11
// speedup vs baseline: 1.0786x; 1.0072x over previous
#include <cuda_runtime.h>

#define POOL 7
#define FM_W 64
#define C2   64   // float2 chunks per pixel (128 fp32 channels)

__global__ __launch_bounds__(224, 7)
void roi_pool_kernel(const float2* __restrict__ fm2,
                     const int* __restrict__ rois,
                     float2* __restrict__ out2,
                     int n_rois)
{
    const int roi = blockIdx.x;
    if (roi >= n_rois) return;

    const int t    = threadIdx.x;
    const int warp = t >> 5;     // 0..6  == output row py
    const int lane = t & 31;

    // ROI descriptor (4-int broadcast load; L1-resident after first touch)
    const int rx1 = __ldg(rois + roi * 4 + 0);
    const int ry1 = __ldg(rois + roi * 4 + 1);
    const int rx2 = __ldg(rois + roi * 4 + 2);
    const int ry2 = __ldg(rois + roi * 4 + 3);

    const float live = ((rx1 | ry1 | rx2 | ry2) == 0) ? 0.0f : 1.0f;

    // ---- y axis: computed once (py = warp), exactly matching the reference:
    //      yc = clip(((j+0.5)*hf)/7 - 0.5, 0, hf-1); y0 = floor(yc)
    const int   hh = max(ry2 - ry1, 1);
    const float hf = (float)hh;
    float yc = __fdiv_rn(((float)warp + 0.5f) * hf, (float)POOL) - 0.5f;
    yc = fminf(fmaxf(yc, 0.0f), hf - 1.0f);
    const int   y0  = (int)floorf(yc);
    const float wy  = yc - (float)y0;
    const int   rb0 = (y0 + ry1) * FM_W;                 // row base, top
    const int   rb1 = (min(y0 + 1, hh - 1) + ry1) * FM_W; // row base, bottom
    const float wyn = (1.0f - wy) * live;                // folded zero-ROI mask
    const float wyp = wy * live;

    const int   ww = max(rx2 - rx1, 1);
    const float wf = (float)ww;

    float2* obase = out2 + (size_t)roi * (POOL * POOL * C2)
                         + warp * (POOL * C2) + lane;

#pragma unroll
    for (int px = 0; px < POOL; px++) {
        // ---- x axis: recomputed by all lanes (trades ALU slots for L1 port) ----
        float xc = __fdiv_rn(((float)px + 0.5f) * wf, (float)POOL) - 0.5f;
        xc = fminf(fmaxf(xc, 0.0f), wf - 1.0f);
        const int   x0  = (int)floorf(xc);
        const float wx  = xc - (float)x0;
        const int   xa0 = x0 + rx1;
        const int   xa1 = min(x0 + 1, ww - 1) + rx1;

        const int o00 = (rb0 + xa0) * C2;
        const int o01 = (rb0 + xa1) * C2;
        const int o10 = (rb1 + xa0) * C2;
        const int o11 = (rb1 + xa1) * C2;

        const float w00 = wyn * (1.0f - wx);
        const float w01 = wyn * wx;
        const float w10 = wyp * (1.0f - wx);
        const float w11 = wyp * wx;

        // sweep A: bytes [0,256) of each pixel; sweep B: bytes [256,512)
        const float2 a00 = __ldg(fm2 + o00 + lane);
        const float2 a01 = __ldg(fm2 + o01 + lane);
        const float2 a10 = __ldg(fm2 + o10 + lane);
        const float2 a11 = __ldg(fm2 + o11 + lane);
        const float2 b00 = __ldg(fm2 + o00 + 32 + lane);
        const float2 b01 = __ldg(fm2 + o01 + 32 + lane);
        const float2 b10 = __ldg(fm2 + o10 + 32 + lane);
        const float2 b11 = __ldg(fm2 + o11 + 32 + lane);

        float2 ra, rb;
        ra.x = fmaf(a00.x, w00, fmaf(a01.x, w01, fmaf(a10.x, w10, a11.x * w11)));
        ra.y = fmaf(a00.y, w00, fmaf(a01.y, w01, fmaf(a10.y, w10, a11.y * w11)));
        rb.x = fmaf(b00.x, w00, fmaf(b01.x, w01, fmaf(b10.x, w10, b11.x * w11)));
        rb.y = fmaf(b00.y, w00, fmaf(b01.y, w01, fmaf(b10.y, w10, b11.y * w11)));

        obase[px * C2]      = ra;
        obase[px * C2 + 32] = rb;
    }
}

extern "C" void kernel_launch(void* const* d_in, const int* in_sizes, int n_in,
                              void* d_out, int out_size)
{
    const float2* fm2  = (const float2*)d_in[0];   // (1,64,64,128) fp32
    const int*    rois = (const int*)d_in[1];      // (1,N,4) int32
    float2*       out2 = (float2*)d_out;           // (1,N,7,7,128) fp32

    const int n_rois = in_sizes[1] / 4;

    roi_pool_kernel<<<n_rois, 224>>>(fm2, rois, out2, n_rois);
}